// round 14
// baseline (speedup 1.0000x reference)
#include <cuda_runtime.h>
#include <cuda_bf16.h>
#include <cstdint>

// Weighted cross entropy:
//   per_sample_i = w[y_i] * (-x[i,y_i] + log(sum_j w[j]*exp(x[i,j])))
//   out = sum_i per_sample_i
//
// x: [B,V] fp32 (1.048 GB, streamed exactly once with .cs -> HBM-bound,
// measured ~7.0 TB/s), y: [B] int64-or-int32 (detected inline), w: [V] fp32
// cached in SMEM.
//
// Layout: 148 persistent CTAs x 1024 threads, each split into 8 independent
// 128-thread row-groups (4 warps) synced only by per-group named barriers.
// 1184 groups chip-wide, 6-7 rows each. Single-kernel design: the final
// reduction runs as a last-CTA-done epilogue (arrival counter), eliminating
// the 6.7us finalize launch. Deterministic: fixed row->group map, fixed
// reduction order everywhere; the arrival atomic only selects WHICH CTA
// performs the (order-fixed) final sum.

#define B_ROWS   8192
#define V_COLS   32000
#define V4       (V_COLS / 4)         // 8000 float4 per row
#define NBLK     148                  // persistent CTAs, 1 per SM
#define NTHREADS 1024
#define GSIZE    128                  // threads per row-group
#define NG       (NTHREADS / GSIZE)   // 8 groups per CTA
#define NGT      (NBLK * NG)          // 1184 groups chip-wide

__device__ double g_cta_partial[NBLK];
__device__ unsigned int g_arrive = 0;   // reset to 0 by the finalizing CTA

__global__ __launch_bounds__(NTHREADS, 1)
void wce_main_kernel(const float* __restrict__ x,
                     const void* __restrict__ yv,
                     const float* __restrict__ w,
                     float* __restrict__ out) {
    extern __shared__ float sw[];      // V_COLS floats = 125 KB weight cache
    __shared__ float  red[32];         // one slot per warp
    __shared__ double gacc[NG];        // per-group partials
    __shared__ int    s_is64;
    __shared__ unsigned int s_ticket;

    const int tid  = threadIdx.x;
    const int lane = tid & 31;
    const int warp = tid >> 5;
    const int g    = warp >> 2;        // row-group 0..7
    const int ltid = tid & (GSIZE - 1);

    // Cache full weight vector in shared memory (vectorized, once per CTA).
    {
        const float4* w4  = reinterpret_cast<const float4*>(w);
        float4*       sw4 = reinterpret_cast<float4*>(sw);
        for (int i = tid; i < V4; i += NTHREADS) sw4[i] = __ldg(&w4[i]);
    }
    // Inline y-dtype probe (overlaps weight load): genuine int64 labels
    // (< 32000) have all-zero high u32 words.
    if (tid == 0) {
        const unsigned int* y32 = (const unsigned int*)yv;
        int is64 = 1;
        #pragma unroll
        for (int k = 0; k < 64; k++)
            if (y32[2 * k + 1] != 0u) is64 = 0;
        s_is64 = is64;
    }
    __syncthreads();
    const int is64 = s_is64;

    double acc = 0.0;

    for (int row = blockIdx.x * NG + g; row < B_ROWS; row += NGT) {
        // Target index for this row.
        long long yi;
        if (is64) yi = reinterpret_cast<const long long*>(yv)[row];
        else      yi = (long long)reinterpret_cast<const int*>(yv)[row];

        // Issue the gather early (group leader only) so it overlaps the stream.
        float xg = 0.0f, wy = 0.0f;
        if (ltid == 0) {
            xg = __ldcs(&x[(size_t)row * V_COLS + (size_t)yi]);
            wy = sw[(int)yi];
        }

        // Stream the row once: s = sum_j w[j] * exp(x[j]).
        // 8000 float4 / 128 threads = 62-63 per thread; unroll x4 batches
        // independent evict-first LDG.128s; dual accumulators cut FFMA RAW.
        const float4* xr  = reinterpret_cast<const float4*>(x) + (size_t)row * V4;
        const float4* sw4 = reinterpret_cast<const float4*>(sw);
        float s0 = 0.0f, s1 = 0.0f;
        #pragma unroll 4
        for (int j = ltid; j < V4; j += GSIZE) {
            float4 v  = __ldcs(&xr[j]);
            float4 ww = sw4[j];
            s0 += ww.x * __expf(v.x);
            s1 += ww.y * __expf(v.y);
            s0 += ww.z * __expf(v.z);
            s1 += ww.w * __expf(v.w);
        }
        float s = s0 + s1;

        // Warp reduce (fixed order), then 4-warp group reduce via named barrier.
        #pragma unroll
        for (int o = 16; o > 0; o >>= 1) s += __shfl_down_sync(0xffffffffu, s, o);
        if (lane == 0) red[warp] = s;
        asm volatile("bar.sync %0, %1;" :: "r"(1 + g), "r"(GSIZE) : "memory");
        if (ltid == 0) {
            float t = red[g * 4] + red[g * 4 + 1] + red[g * 4 + 2] + red[g * 4 + 3];
            acc += (double)(wy * (logf(t) - xg));
        }
        asm volatile("bar.sync %0, %1;" :: "r"(1 + g), "r"(GSIZE) : "memory");
    }

    // --- Epilogue: CTA-level combine, then last-CTA-done final sum. ---
    if (ltid == 0) gacc[g] = acc;
    __syncthreads();
    if (tid == 0) {
        double c = 0.0;
        #pragma unroll
        for (int i = 0; i < NG; i++) c += gacc[i];   // fixed order
        g_cta_partial[blockIdx.x] = c;
        __threadfence();
        // Arrival ticket: selects WHICH CTA finalizes; result order is fixed.
        s_ticket = atomicAdd(&g_arrive, 1u);
    }
    __syncthreads();
    if (s_ticket == NBLK - 1) {
        // Last CTA: warp 0 loads the 148 partials with full MLP, then thread 0
        // sums them in fixed index order (deterministic).
        __threadfence();
        __shared__ double sp[NBLK];
        if (tid < NBLK) sp[tid] = g_cta_partial[tid];
        __syncthreads();
        if (tid == 0) {
            double t = 0.0;
            #pragma unroll 4
            for (int i = 0; i < NBLK; i++) t += sp[i];
            out[0] = (float)t;
            g_arrive = 0;            // reset for next graph replay
        }
    }
}

extern "C" void kernel_launch(void* const* d_in, const int* in_sizes, int n_in,
                              void* d_out, int out_size) {
    const float* x = (const float*)d_in[0];
    const void*  y = d_in[1];
    const float* w = (const float*)d_in[2];
    float* out = (float*)d_out;

    // 125 KB dynamic smem for the weight cache. Host-side attribute set:
    // idempotent, deterministic, not a stream op -> capture-safe.
    cudaFuncSetAttribute(wce_main_kernel,
                         cudaFuncAttributeMaxDynamicSharedMemorySize,
                         V_COLS * (int)sizeof(float));

    wce_main_kernel<<<NBLK, NTHREADS, V_COLS * sizeof(float)>>>(x, y, w, out);
}

// round 15
// speedup vs baseline: 1.0475x; 1.0475x over previous
#include <cuda_runtime.h>
#include <cuda_bf16.h>
#include <cstdint>

// Weighted cross entropy:
//   per_sample_i = w[y_i] * (-x[i,y_i] + log(sum_j w[j]*exp(x[i,j])))
//   out = sum_i per_sample_i
//
// x: [B,V] fp32 (1.048 GB, streamed exactly once with .cs -> HBM-bound),
// y: [B] int64-or-int32 (detected inline), w: [V] fp32 cached in SMEM.
//
// 148 persistent CTAs x 1024 threads; 8 independent 128-thread row-groups per
// CTA (named-barrier sync only) -> reduction tails decoupled, DRAM queue kept
// full by sibling groups. Single kernel: final sum via last-CTA-done epilogue
// (register-lean: warp-0 strided loads + shfl tree, no shared staging).
// Deterministic: fixed row->group map and fixed-shape reduction trees; the
// arrival atomic only selects WHICH CTA runs the (order-fixed) final sum.

#define B_ROWS   8192
#define V_COLS   32000
#define V4       (V_COLS / 4)         // 8000 float4 per row
#define NBLK     148                  // persistent CTAs, 1 per SM
#define NTHREADS 1024
#define GSIZE    128                  // threads per row-group
#define NG       (NTHREADS / GSIZE)   // 8 groups per CTA
#define NGT      (NBLK * NG)          // 1184 groups chip-wide

__device__ double g_cta_partial[NBLK];
__device__ unsigned int g_arrive = 0;   // reset by the finalizing CTA

__global__ __launch_bounds__(NTHREADS, 1)
void wce_main_kernel(const float* __restrict__ x,
                     const void* __restrict__ yv,
                     const float* __restrict__ w,
                     float* __restrict__ out) {
    extern __shared__ float sw[];      // V_COLS floats = 125 KB weight cache
    __shared__ float  red[32];         // one slot per warp
    __shared__ double gacc[NG];        // per-group partials
    __shared__ int    s_is64;
    __shared__ unsigned int s_ticket;

    const int tid  = threadIdx.x;
    const int lane = tid & 31;
    const int warp = tid >> 5;
    const int g    = warp >> 2;        // row-group 0..7
    const int ltid = tid & (GSIZE - 1);

    // Cache full weight vector in shared memory (vectorized, once per CTA).
    {
        const float4* w4  = reinterpret_cast<const float4*>(w);
        float4*       sw4 = reinterpret_cast<float4*>(sw);
        for (int i = tid; i < V4; i += NTHREADS) sw4[i] = __ldg(&w4[i]);
    }
    // Inline y-dtype probe (overlaps weight load): genuine int64 labels
    // (< 32000) have all-zero high u32 words.
    if (tid == 0) {
        const unsigned int* y32 = (const unsigned int*)yv;
        int is64 = 1;
        #pragma unroll
        for (int k = 0; k < 64; k++)
            if (y32[2 * k + 1] != 0u) is64 = 0;
        s_is64 = is64;
    }
    __syncthreads();
    const int is64 = s_is64;

    double acc = 0.0;

    for (int row = blockIdx.x * NG + g; row < B_ROWS; row += NGT) {
        // Target index for this row.
        long long yi;
        if (is64) yi = reinterpret_cast<const long long*>(yv)[row];
        else      yi = (long long)reinterpret_cast<const int*>(yv)[row];

        // Issue the gather early (group leader only) so it overlaps the stream.
        float xg = 0.0f, wy = 0.0f;
        if (ltid == 0) {
            xg = __ldcs(&x[(size_t)row * V_COLS + (size_t)yi]);
            wy = sw[(int)yi];
        }

        // Stream the row once: s = sum_j w[j] * exp(x[j]).
        // 8000 float4 / 128 threads; unroll x4 batches independent evict-first
        // LDG.128s (MLP); dual accumulators cut the FFMA RAW chain.
        const float4* xr  = reinterpret_cast<const float4*>(x) + (size_t)row * V4;
        const float4* sw4 = reinterpret_cast<const float4*>(sw);
        float s0 = 0.0f, s1 = 0.0f;
        #pragma unroll 4
        for (int j = ltid; j < V4; j += GSIZE) {
            float4 v  = __ldcs(&xr[j]);
            float4 ww = sw4[j];
            s0 += ww.x * __expf(v.x);
            s1 += ww.y * __expf(v.y);
            s0 += ww.z * __expf(v.z);
            s1 += ww.w * __expf(v.w);
        }
        float s = s0 + s1;

        // Warp reduce (fixed order), then 4-warp group reduce via named barrier.
        #pragma unroll
        for (int o = 16; o > 0; o >>= 1) s += __shfl_down_sync(0xffffffffu, s, o);
        if (lane == 0) red[warp] = s;
        asm volatile("bar.sync %0, %1;" :: "r"(1 + g), "r"(GSIZE) : "memory");
        if (ltid == 0) {
            float t = red[g * 4] + red[g * 4 + 1] + red[g * 4 + 2] + red[g * 4 + 3];
            acc += (double)(wy * (logf(t) - xg));
        }
        asm volatile("bar.sync %0, %1;" :: "r"(1 + g), "r"(GSIZE) : "memory");
    }

    // --- Epilogue: CTA combine, then last-CTA-done final sum (lean). ---
    if (ltid == 0) gacc[g] = acc;
    __syncthreads();
    if (tid == 0) {
        double c = 0.0;
        #pragma unroll
        for (int i = 0; i < NG; i++) c += gacc[i];      // fixed order
        g_cta_partial[blockIdx.x] = c;
        __threadfence();
        s_ticket = atomicAdd(&g_arrive, 1u);            // selects finalizer only
    }
    __syncthreads();
    if (s_ticket == NBLK - 1 && warp == 0) {
        __threadfence();
        // Fixed per-lane strided order + fixed-shape shfl tree -> deterministic.
        double t = 0.0;
        for (int i = lane; i < NBLK; i += 32) t += g_cta_partial[i];
        #pragma unroll
        for (int o = 16; o > 0; o >>= 1) t += __shfl_down_sync(0xffffffffu, t, o);
        if (lane == 0) {
            out[0] = (float)t;
            g_arrive = 0;            // reset for next graph replay
        }
    }
}

extern "C" void kernel_launch(void* const* d_in, const int* in_sizes, int n_in,
                              void* d_out, int out_size) {
    const float* x = (const float*)d_in[0];
    const void*  y = d_in[1];
    const float* w = (const float*)d_in[2];
    float* out = (float*)d_out;

    // 125 KB dynamic smem for the weight cache. Host-side attribute set:
    // idempotent, deterministic, not a stream op -> capture-safe.
    cudaFuncSetAttribute(wce_main_kernel,
                         cudaFuncAttributeMaxDynamicSharedMemorySize,
                         V_COLS * (int)sizeof(float));

    wce_main_kernel<<<NBLK, NTHREADS, V_COLS * sizeof(float)>>>(x, y, w, out);
}